// round 6
// baseline (speedup 1.0000x reference)
#include <cuda_runtime.h>
#include <stdint.h>

#define NROWS   500000
#define NCOLS   64
#define NELEM   (NROWS * NCOLS)        // 32,000,000
#define NF4     (NELEM / 4)            // 8,000,000
#define NBINS   31
#define BLOCK   256
#define BPSM    5
#define NBLK    (148 * BPSM)           // 740
#define T       (NBLK * BLOCK)         // 189,440
#define UNROLL  5

__device__ unsigned int g_hist_all[32];
__device__ unsigned int g_hist_t[32];
__device__ unsigned int g_done;

// float bits of fma(sigmoid(x),30,12582911.5): low 5 bits == bin (0..30)
__device__ __forceinline__ unsigned int ybits_of(float x) {
    float t = x * -1.4426950408889634f;
    float e; asm("ex2.approx.f32 %0, %1;" : "=f"(e) : "f"(t));   // e^-x
    float d = e + 1.0f;
    float v; asm("rcp.approx.f32 %0, %1;" : "=f"(v) : "f"(d));   // sigmoid
    float y = fmaf(v, 30.0f, 12582911.5f);                       // 1.5*2^23 - 0.5
    return __float_as_uint(y);
}

// one 32-element slot: lane L's acc += #lanes whose bin == L
__device__ __forceinline__ void slot(float x, unsigned int x0, unsigned int x1,
                                     unsigned int x2, unsigned int x3,
                                     unsigned int x4, unsigned int& acc) {
    unsigned int u = ybits_of(x);
    unsigned int B0 = __ballot_sync(0xffffffffu, u & 1u);
    unsigned int B1 = __ballot_sync(0xffffffffu, u & 2u);
    unsigned int B2 = __ballot_sync(0xffffffffu, u & 4u);
    unsigned int B3 = __ballot_sync(0xffffffffu, u & 8u);
    unsigned int B4 = __ballot_sync(0xffffffffu, u & 16u);
    unsigned int m = (B0 ^ x0) & (B1 ^ x1) & (B2 ^ x2) & (B3 ^ x3) & (B4 ^ x4);
    acc += __popc(m);
}

__device__ __forceinline__ void truecheck(float4 v, int f, int tg,
                                          unsigned int* strue) {
    if ((tg >> 2) == (f & 15)) {               // this float4 holds the true col
        int c = tg & 3;
        float xs = (c & 2) ? ((c & 1) ? v.w : v.z) : ((c & 1) ? v.y : v.x);
        atomicAdd(&strue[ybits_of(xs) & 31u], 1u);
    }
}

__global__ __launch_bounds__(BLOCK, BPSM)
void auc_kernel(const float4* __restrict__ o4, const int* __restrict__ tgt,
                float* __restrict__ out) {
    __shared__ unsigned int wred[(BLOCK / 32) * 32];
    __shared__ unsigned int strue[32];
    __shared__ int s_last;

    const int tid  = threadIdx.x;
    const int lane = tid & 31;
    const int wid  = tid >> 5;
    if (tid < 32) strue[tid] = 0u;
    __syncthreads();

    // lane-constant slice masks: x_j = (lane bit j) ? 0 : ~0
    const unsigned int x0 = (lane & 1)  ? 0u : 0xffffffffu;
    const unsigned int x1 = (lane & 2)  ? 0u : 0xffffffffu;
    const unsigned int x2 = (lane & 4)  ? 0u : 0xffffffffu;
    const unsigned int x3 = (lane & 8)  ? 0u : 0xffffffffu;
    const unsigned int x4 = (lane & 16) ? 0u : 0xffffffffu;

    unsigned int acc = 0u;   // count of bin==lane

    int i0 = blockIdx.x * BLOCK + tid;
    // main loop: trip count uniform across whole grid (8 iters)
    while (i0 + (UNROLL - 1) * T < NF4) {
        int f0 = i0, f1 = i0 + T, f2 = i0 + 2 * T, f3 = i0 + 3 * T, f4 = i0 + 4 * T;
        float4 v0 = __ldg(o4 + f0);
        float4 v1 = __ldg(o4 + f1);
        float4 v2 = __ldg(o4 + f2);
        float4 v3 = __ldg(o4 + f3);
        float4 v4 = __ldg(o4 + f4);
        int tg0 = __ldg(tgt + (f0 >> 4));
        int tg1 = __ldg(tgt + (f1 >> 4));
        int tg2 = __ldg(tgt + (f2 >> 4));
        int tg3 = __ldg(tgt + (f3 >> 4));
        int tg4 = __ldg(tgt + (f4 >> 4));

        slot(v0.x, x0,x1,x2,x3,x4, acc); slot(v0.y, x0,x1,x2,x3,x4, acc);
        slot(v0.z, x0,x1,x2,x3,x4, acc); slot(v0.w, x0,x1,x2,x3,x4, acc);
        slot(v1.x, x0,x1,x2,x3,x4, acc); slot(v1.y, x0,x1,x2,x3,x4, acc);
        slot(v1.z, x0,x1,x2,x3,x4, acc); slot(v1.w, x0,x1,x2,x3,x4, acc);
        slot(v2.x, x0,x1,x2,x3,x4, acc); slot(v2.y, x0,x1,x2,x3,x4, acc);
        slot(v2.z, x0,x1,x2,x3,x4, acc); slot(v2.w, x0,x1,x2,x3,x4, acc);
        slot(v3.x, x0,x1,x2,x3,x4, acc); slot(v3.y, x0,x1,x2,x3,x4, acc);
        slot(v3.z, x0,x1,x2,x3,x4, acc); slot(v3.w, x0,x1,x2,x3,x4, acc);
        slot(v4.x, x0,x1,x2,x3,x4, acc); slot(v4.y, x0,x1,x2,x3,x4, acc);
        slot(v4.z, x0,x1,x2,x3,x4, acc); slot(v4.w, x0,x1,x2,x3,x4, acc);

        truecheck(v0, f0, tg0, strue);
        truecheck(v1, f1, tg1, strue);
        truecheck(v2, f2, tg2, strue);
        truecheck(v3, f3, tg3, strue);
        truecheck(v4, f4, tg4, strue);
        i0 += UNROLL * T;
    }
    // remainder: warp-uniform trip counts (NF4 and boundaries 32-aligned)
    while (i0 < NF4) {
        float4 v = __ldg(o4 + i0);
        int tg = __ldg(tgt + (i0 >> 4));
        slot(v.x, x0,x1,x2,x3,x4, acc); slot(v.y, x0,x1,x2,x3,x4, acc);
        slot(v.z, x0,x1,x2,x3,x4, acc); slot(v.w, x0,x1,x2,x3,x4, acc);
        truecheck(v, i0, tg, strue);
        i0 += T;
    }

    // block reduction of per-lane bin counts
    wred[wid * 32 + lane] = acc;
    __syncthreads();
    if (wid == 0) {
        unsigned int s = 0;
        #pragma unroll
        for (int w = 0; w < BLOCK / 32; w++) s += wred[w * 32 + lane];
        if (lane < NBINS && s) atomicAdd(&g_hist_all[lane], s);
    }
    if (tid < NBINS) {
        unsigned int s = strue[tid];
        if (s) atomicAdd(&g_hist_t[tid], s);
    }

    // last-block finalize
    if (tid == 0) {
        __threadfence();
        unsigned int prev = atomicAdd(&g_done, 1u);
        s_last = (prev == gridDim.x - 1);
    }
    __syncthreads();
    if (s_last && tid == 0) {
        __threadfence();
        volatile unsigned int* vha = g_hist_all;
        volatile unsigned int* vht = g_hist_t;
        double ht[NBINS], ha[NBINS], trues = 0.0;
        for (int b = 0; b < NBINS; b++) {
            ht[b] = (double)vht[b];
            ha[b] = (double)vha[b];
            trues += ht[b];
        }
        double falses = (double)NELEM - trues;

        double tp_asc[30], fp_asc[30], ct = 0.0, cf = 0.0;
        for (int j = 0; j < 30; j++) {
            ct += ht[j];
            cf += (ha[j] - ht[j]);
            tp_asc[j] = trues  - ct;
            fp_asc[j] = falses - cf;
        }
        const double eps = 1e-8;
        double area = 0.0, pt = 0.0, pf = 0.0;
        for (int i = 0; i < 30; i++) {
            double tpr = tp_asc[29 - i] / (trues  + eps);
            double fpr = fp_asc[29 - i] / (falses + eps);
            double wdt = fabs(fpr - pf);
            double mn = fmin(tpr, pt), mx = fmax(tpr, pt);
            area += wdt * mn + 0.5 * wdt * (mx - mn);
            pt = tpr; pf = fpr;
        }
        out[0] = (float)area;

        for (int b = 0; b < 32; b++) { g_hist_all[b] = 0u; g_hist_t[b] = 0u; }
        g_done = 0u;
    }
}

extern "C" void kernel_launch(void* const* d_in, const int* in_sizes, int n_in,
                              void* d_out, int out_size) {
    const float* output = (const float*)d_in[0];
    const int*   target = (const int*)d_in[1];
    if (n_in >= 2 && in_sizes[0] == NROWS && in_sizes[1] == NELEM) {
        output = (const float*)d_in[1];
        target = (const int*)d_in[0];
    }
    auc_kernel<<<NBLK, BLOCK>>>((const float4*)output, target, (float*)d_out);
}

// round 7
// speedup vs baseline: 1.4286x; 1.4286x over previous
#include <cuda_runtime.h>
#include <stdint.h>

#define NROWS   500000
#define NCOLS   64
#define NELEM   (NROWS * NCOLS)        // 32,000,000
#define NF4     (NELEM / 4)            // 8,000,000
#define NBINS   31
#define BLOCK   256
#define BPSM    6
#define NBLK    (148 * BPSM)           // 888
#define T       (NBLK * BLOCK)         // 227,328

__device__ unsigned int g_hist_all[32];
__device__ unsigned int g_hist_t[32];
__device__ unsigned int g_done;

// float bits of fma(sigmoid(x),30,12582911.5): value = 12582912 + floor(30*sigmoid)
__device__ __forceinline__ unsigned int ybits_of(float x) {
    float t = x * -1.4426950408889634f;
    float e; asm("ex2.approx.f32 %0, %1;" : "=f"(e) : "f"(t));   // e^-x
    float d = e + 1.0f;
    float v; asm("rcp.approx.f32 %0, %1;" : "=f"(v) : "f"(d));   // sigmoid
    float y = fmaf(v, 30.0f, 12582911.5f);                       // 1.5*2^23 - 0.5
    return __float_as_uint(y);
}

// hist[bin][tid]++ ; byte offset = (ybits<<10) mod 2^32 == bin*1024
// (0x4B400000<<10 wraps to 0, BLOCK*4 == 1024)
__device__ __forceinline__ void binc(char* __restrict__ hrow, float x) {
    unsigned int off = ybits_of(x) << 10;
    unsigned int* p = (unsigned int*)(hrow + off);
    (*p)++;
}

__global__ __launch_bounds__(BLOCK, BPSM)
void auc_kernel(const float4* __restrict__ o4, const float* __restrict__ os,
                const int* __restrict__ tgt, float* __restrict__ out) {
    __shared__ unsigned int hist[NBINS * BLOCK];   // 31,744 B, conflict-free
    __shared__ unsigned int strue[32];
    __shared__ int s_last;

    const int tid = threadIdx.x;
    #pragma unroll
    for (int i = tid; i < NBINS * BLOCK; i += BLOCK) hist[i] = 0u;
    if (tid < 32) strue[tid] = 0u;
    __syncthreads();

    const int gtid = blockIdx.x * BLOCK + tid;

    // ---- Phase A: true-class elements (1 scattered gather per row) ----
    for (int r = gtid; r < NROWS; r += T) {
        int   tg = __ldg(tgt + r);
        float xs = __ldg(os + r * NCOLS + tg);
        atomicAdd(&strue[ybits_of(xs) & 31u], 1u);
    }

    // ---- Phase B: pure histogram over all elements ----
    char* hrow = (char*)hist + tid * 4;
    int i0 = gtid;
    while (i0 + 3 * T < NF4) {
        float4 v0 = __ldg(o4 + i0);
        float4 v1 = __ldg(o4 + i0 + T);
        float4 v2 = __ldg(o4 + i0 + 2 * T);
        float4 v3 = __ldg(o4 + i0 + 3 * T);

        binc(hrow, v0.x); binc(hrow, v0.y); binc(hrow, v0.z); binc(hrow, v0.w);
        binc(hrow, v1.x); binc(hrow, v1.y); binc(hrow, v1.z); binc(hrow, v1.w);
        binc(hrow, v2.x); binc(hrow, v2.y); binc(hrow, v2.z); binc(hrow, v2.w);
        binc(hrow, v3.x); binc(hrow, v3.y); binc(hrow, v3.z); binc(hrow, v3.w);
        i0 += 4 * T;
    }
    while (i0 < NF4) {
        float4 v = __ldg(o4 + i0);
        binc(hrow, v.x); binc(hrow, v.y); binc(hrow, v.z); binc(hrow, v.w);
        i0 += T;
    }
    __syncthreads();

    // ---- block reduction -> global atomics ----
    int lane = tid & 31, wid = tid >> 5;           // 8 warps
    for (int b = wid; b < NBINS; b += (BLOCK / 32)) {
        unsigned int s = 0;
        #pragma unroll
        for (int k = 0; k < BLOCK / 32; k++) s += hist[b * BLOCK + k * 32 + lane];
        #pragma unroll
        for (int o = 16; o; o >>= 1) s += __shfl_down_sync(0xffffffffu, s, o);
        if (lane == 0 && s) atomicAdd(&g_hist_all[b], s);
    }
    if (tid < NBINS) {
        unsigned int s = strue[tid];
        if (s) atomicAdd(&g_hist_t[tid], s);
    }

    // ---- last-block finalize ----
    if (tid == 0) {
        __threadfence();
        unsigned int prev = atomicAdd(&g_done, 1u);
        s_last = (prev == gridDim.x - 1);
    }
    __syncthreads();
    if (s_last && tid == 0) {
        __threadfence();
        volatile unsigned int* vha = g_hist_all;
        volatile unsigned int* vht = g_hist_t;
        double ht[NBINS], ha[NBINS], trues = 0.0;
        for (int b = 0; b < NBINS; b++) {
            ht[b] = (double)vht[b];
            ha[b] = (double)vha[b];
            trues += ht[b];
        }
        double falses = (double)NELEM - trues;

        double tp_asc[30], fp_asc[30], ct = 0.0, cf = 0.0;
        for (int j = 0; j < 30; j++) {
            ct += ht[j];
            cf += (ha[j] - ht[j]);
            tp_asc[j] = trues  - ct;
            fp_asc[j] = falses - cf;
        }
        const double eps = 1e-8;
        double area = 0.0, pt = 0.0, pf = 0.0;
        for (int i = 0; i < 30; i++) {
            double tpr = tp_asc[29 - i] / (trues  + eps);
            double fpr = fp_asc[29 - i] / (falses + eps);
            double wdt = fabs(fpr - pf);
            double mn = fmin(tpr, pt), mx = fmax(tpr, pt);
            area += wdt * mn + 0.5 * wdt * (mx - mn);
            pt = tpr; pf = fpr;
        }
        out[0] = (float)area;

        for (int b = 0; b < 32; b++) { g_hist_all[b] = 0u; g_hist_t[b] = 0u; }
        g_done = 0u;
    }
}

extern "C" void kernel_launch(void* const* d_in, const int* in_sizes, int n_in,
                              void* d_out, int out_size) {
    const float* output = (const float*)d_in[0];
    const int*   target = (const int*)d_in[1];
    if (n_in >= 2 && in_sizes[0] == NROWS && in_sizes[1] == NELEM) {
        output = (const float*)d_in[1];
        target = (const int*)d_in[0];
    }
    auc_kernel<<<NBLK, BLOCK>>>((const float4*)output, output, target,
                                (float*)d_out);
}

// round 8
// speedup vs baseline: 1.6527x; 1.1569x over previous
#include <cuda_runtime.h>
#include <stdint.h>

#define NROWS   500000
#define NCOLS   64
#define NELEM   (NROWS * NCOLS)        // 32,000,000
#define NF4     (NELEM / 4)            // 8,000,000
#define NBINS   31
#define BLOCK   256
#define BPSM    6
#define NBLK    (148 * BPSM)           // 888
#define T       (NBLK * BLOCK)         // 227,328

__device__ unsigned int g_hist_all[32];
__device__ unsigned int g_hist_t[32];
__device__ unsigned int g_done;

// Exact floor(30*sigmoid(x)) in 0..30 (two-step: both constants representable).
__device__ __forceinline__ unsigned int bin_of(float x) {
    float t = x * -1.4426950408889634f;
    float e; asm("ex2.approx.f32 %0, %1;" : "=f"(e) : "f"(t));   // e^-x
    float d = e + 1.0f;
    float v; asm("rcp.approx.f32 %0, %1;" : "=f"(v) : "f"(d));   // sigmoid (0,1]
    float z = fmaf(v, 30.0f, -0.5f);                              // (-0.5, 29.5]
    float y = z + 12582912.0f;                                    // RN -> floor
    return __float_as_uint(y) & 31u;                              // bits low5 = bin
}

__global__ __launch_bounds__(BLOCK, BPSM)
void auc_kernel(const float4* __restrict__ o4, const int* __restrict__ tgt,
                float* __restrict__ out) {
    // 32 bank-spread copies: shist[bin*32 + lane]; bank == lane, conflict-free.
    __shared__ unsigned int shist[NBINS * 32];     // 3,968 B
    __shared__ unsigned int strue[32];
    __shared__ int s_last;

    const int tid  = threadIdx.x;
    const int lane = tid & 31;
    #pragma unroll
    for (int i = tid; i < NBINS * 32; i += BLOCK) shist[i] = 0u;
    if (tid < 32) strue[tid] = 0u;
    __syncthreads();

    unsigned int* hl = &shist[lane];

    int i0 = blockIdx.x * BLOCK + tid;
    while (i0 + 3 * T < NF4) {
        int f0 = i0, f1 = i0 + T, f2 = i0 + 2 * T, f3 = i0 + 3 * T;
        float4 v0 = __ldg(o4 + f0);
        float4 v1 = __ldg(o4 + f1);
        float4 v2 = __ldg(o4 + f2);
        float4 v3 = __ldg(o4 + f3);
        int tg0 = __ldg(tgt + (f0 >> 4));
        int tg1 = __ldg(tgt + (f1 >> 4));
        int tg2 = __ldg(tgt + (f2 >> 4));
        int tg3 = __ldg(tgt + (f3 >> 4));

        #pragma unroll
        for (int k = 0; k < 4; k++) {
            float4 x = (k == 0) ? v0 : (k == 1) ? v1 : (k == 2) ? v2 : v3;
            int    f = (k == 0) ? f0 : (k == 1) ? f1 : (k == 2) ? f2 : f3;
            int    tg = (k == 0) ? tg0 : (k == 1) ? tg1 : (k == 2) ? tg2 : tg3;
            unsigned int b0 = bin_of(x.x), b1 = bin_of(x.y);
            unsigned int b2 = bin_of(x.z), b3 = bin_of(x.w);
            atomicAdd(hl + (b0 << 5), 1u);
            atomicAdd(hl + (b1 << 5), 1u);
            atomicAdd(hl + (b2 << 5), 1u);
            atomicAdd(hl + (b3 << 5), 1u);
            if ((tg >> 2) == (f & 15)) {
                int j = tg & 3;
                unsigned int bb = (j & 2) ? ((j & 1) ? b3 : b2)
                                          : ((j & 1) ? b1 : b0);
                atomicAdd(&strue[bb], 1u);
            }
        }
        i0 += 4 * T;
    }
    while (i0 < NF4) {
        float4 x = __ldg(o4 + i0);
        int tg = __ldg(tgt + (i0 >> 4));
        unsigned int b0 = bin_of(x.x), b1 = bin_of(x.y);
        unsigned int b2 = bin_of(x.z), b3 = bin_of(x.w);
        atomicAdd(hl + (b0 << 5), 1u);
        atomicAdd(hl + (b1 << 5), 1u);
        atomicAdd(hl + (b2 << 5), 1u);
        atomicAdd(hl + (b3 << 5), 1u);
        if ((tg >> 2) == (i0 & 15)) {
            int j = tg & 3;
            unsigned int bb = (j & 2) ? ((j & 1) ? b3 : b2)
                                      : ((j & 1) ? b1 : b0);
            atomicAdd(&strue[bb], 1u);
        }
        i0 += T;
    }
    __syncthreads();

    // block reduction: 8 warps cover 31 bins; lane-sum via shfl
    int wid = tid >> 5;
    for (int b = wid; b < NBINS; b += (BLOCK / 32)) {
        unsigned int s = shist[(b << 5) + lane];
        #pragma unroll
        for (int o = 16; o; o >>= 1) s += __shfl_down_sync(0xffffffffu, s, o);
        if (lane == 0 && s) atomicAdd(&g_hist_all[b], s);
    }
    if (tid < NBINS) {
        unsigned int s = strue[tid];
        if (s) atomicAdd(&g_hist_t[tid], s);
    }

    // last-block finalize
    if (tid == 0) {
        __threadfence();
        unsigned int prev = atomicAdd(&g_done, 1u);
        s_last = (prev == gridDim.x - 1);
    }
    __syncthreads();
    if (s_last && tid == 0) {
        __threadfence();
        volatile unsigned int* vha = g_hist_all;
        volatile unsigned int* vht = g_hist_t;
        double ht[NBINS], ha[NBINS], trues = 0.0;
        for (int b = 0; b < NBINS; b++) {
            ht[b] = (double)vht[b];
            ha[b] = (double)vha[b];
            trues += ht[b];
        }
        double falses = (double)NELEM - trues;

        double tp_asc[30], fp_asc[30], ct = 0.0, cf = 0.0;
        for (int j = 0; j < 30; j++) {
            ct += ht[j];
            cf += (ha[j] - ht[j]);
            tp_asc[j] = trues  - ct;
            fp_asc[j] = falses - cf;
        }
        const double eps = 1e-8;
        double area = 0.0, pt = 0.0, pf = 0.0;
        for (int i = 0; i < 30; i++) {
            double tpr = tp_asc[29 - i] / (trues  + eps);
            double fpr = fp_asc[29 - i] / (falses + eps);
            double wdt = fabs(fpr - pf);
            double mn = fmin(tpr, pt), mx = fmax(tpr, pt);
            area += wdt * mn + 0.5 * wdt * (mx - mn);
            pt = tpr; pf = fpr;
        }
        out[0] = (float)area;

        for (int b = 0; b < 32; b++) { g_hist_all[b] = 0u; g_hist_t[b] = 0u; }
        g_done = 0u;
    }
}

extern "C" void kernel_launch(void* const* d_in, const int* in_sizes, int n_in,
                              void* d_out, int out_size) {
    const float* output = (const float*)d_in[0];
    const int*   target = (const int*)d_in[1];
    if (n_in >= 2 && in_sizes[0] == NROWS && in_sizes[1] == NELEM) {
        output = (const float*)d_in[1];
        target = (const int*)d_in[0];
    }
    auc_kernel<<<NBLK, BLOCK>>>((const float4*)output, target, (float*)d_out);
}

// round 9
// speedup vs baseline: 1.8182x; 1.1001x over previous
#include <cuda_runtime.h>
#include <stdint.h>

#define NROWS   500000
#define NCOLS   64
#define NELEM   (NROWS * NCOLS)        // 32,000,000
#define NF4     (NELEM / 4)            // 8,000,000
#define NBINS   31
#define BLOCK   256
#define BPSM    4
#define NBLK    (148 * BPSM)           // 592
#define T       (NBLK * BLOCK)         // 151,552

__device__ unsigned int g_hist_all[32];
__device__ unsigned int g_hist_t[32];
__device__ unsigned int g_done;

// Exact floor(30*sigmoid(x)) in 0..30.
__device__ __forceinline__ unsigned int bin_of(float x) {
    float t = x * -1.4426950408889634f;
    float e; asm("ex2.approx.f32 %0, %1;" : "=f"(e) : "f"(t));   // e^-x
    float d = e + 1.0f;
    float v; asm("rcp.approx.f32 %0, %1;" : "=f"(v) : "f"(d));   // sigmoid (0,1]
    float z = fmaf(v, 30.0f, -0.5f);                              // (-0.5, 29.5]
    float y = z + 12582912.0f;                                    // RN -> floor
    return __float_as_uint(y) & 31u;
}

__device__ __forceinline__ void hist4(unsigned int* hl, float4 v) {
    atomicAdd(hl + (bin_of(v.x) << 5), 1u);
    atomicAdd(hl + (bin_of(v.y) << 5), 1u);
    atomicAdd(hl + (bin_of(v.z) << 5), 1u);
    atomicAdd(hl + (bin_of(v.w) << 5), 1u);
}

__global__ __launch_bounds__(BLOCK, BPSM)
void auc_kernel(const float4* __restrict__ o4, const float* __restrict__ os,
                const int* __restrict__ tgt, float* __restrict__ out) {
    // 32 bank-spread copies: shist[bin*32 + lane]; bank == lane, conflict-free.
    __shared__ unsigned int shist[NBINS * 32];     // 3,968 B
    __shared__ unsigned int strue[32];
    __shared__ int s_last;

    const int tid  = threadIdx.x;
    const int lane = tid & 31;
    #pragma unroll
    for (int i = tid; i < NBINS * 32; i += BLOCK) shist[i] = 0u;
    if (tid < 32) strue[tid] = 0u;
    __syncthreads();

    const int gtid = blockIdx.x * BLOCK + tid;

    // ---- Phase A: true-class elements (scattered gather, ~3 rows/thread) ----
    for (int r = gtid; r < NROWS; r += T) {
        int   tg = __ldg(tgt + r);
        float xs = __ldg(os + r * NCOLS + tg);
        atomicAdd(&strue[bin_of(xs)], 1u);
    }

    // ---- Phase B: pipelined pure histogram ----
    unsigned int* hl = &shist[lane];
    int i = gtid;
    if (i + 3 * T < NF4) {
        float4 c0 = __ldg(o4 + i);
        float4 c1 = __ldg(o4 + i + T);
        float4 c2 = __ldg(o4 + i + 2 * T);
        float4 c3 = __ldg(o4 + i + 3 * T);
        int nx = i + 4 * T;
        while (nx + 3 * T < NF4) {
            // prefetch next mega-iter while current one is consumed
            float4 n0 = __ldg(o4 + nx);
            float4 n1 = __ldg(o4 + nx + T);
            float4 n2 = __ldg(o4 + nx + 2 * T);
            float4 n3 = __ldg(o4 + nx + 3 * T);
            hist4(hl, c0); hist4(hl, c1); hist4(hl, c2); hist4(hl, c3);
            c0 = n0; c1 = n1; c2 = n2; c3 = n3;
            nx += 4 * T;
        }
        hist4(hl, c0); hist4(hl, c1); hist4(hl, c2); hist4(hl, c3);
        i = nx;
    }
    while (i < NF4) {
        float4 v = __ldg(o4 + i);
        hist4(hl, v);
        i += T;
    }
    __syncthreads();

    // ---- block reduction: 8 warps cover 31 bins; lane-sum via shfl ----
    int wid = tid >> 5;
    for (int b = wid; b < NBINS; b += (BLOCK / 32)) {
        unsigned int s = shist[(b << 5) + lane];
        #pragma unroll
        for (int o = 16; o; o >>= 1) s += __shfl_down_sync(0xffffffffu, s, o);
        if (lane == 0 && s) atomicAdd(&g_hist_all[b], s);
    }
    if (tid < NBINS) {
        unsigned int s = strue[tid];
        if (s) atomicAdd(&g_hist_t[tid], s);
    }

    // ---- last-block finalize ----
    if (tid == 0) {
        __threadfence();
        unsigned int prev = atomicAdd(&g_done, 1u);
        s_last = (prev == gridDim.x - 1);
    }
    __syncthreads();
    if (s_last && tid == 0) {
        __threadfence();
        volatile unsigned int* vha = g_hist_all;
        volatile unsigned int* vht = g_hist_t;
        double ht[NBINS], ha[NBINS], trues = 0.0;
        for (int b = 0; b < NBINS; b++) {
            ht[b] = (double)vht[b];
            ha[b] = (double)vha[b];
            trues += ht[b];
        }
        double falses = (double)NELEM - trues;

        double tp_asc[30], fp_asc[30], ct = 0.0, cf = 0.0;
        for (int j = 0; j < 30; j++) {
            ct += ht[j];
            cf += (ha[j] - ht[j]);
            tp_asc[j] = trues  - ct;
            fp_asc[j] = falses - cf;
        }
        const double eps = 1e-8;
        double area = 0.0, pt = 0.0, pf = 0.0;
        for (int k = 0; k < 30; k++) {
            double tpr = tp_asc[29 - k] / (trues  + eps);
            double fpr = fp_asc[29 - k] / (falses + eps);
            double wdt = fabs(fpr - pf);
            double mn = fmin(tpr, pt), mx = fmax(tpr, pt);
            area += wdt * mn + 0.5 * wdt * (mx - mn);
            pt = tpr; pf = fpr;
        }
        out[0] = (float)area;

        for (int b = 0; b < 32; b++) { g_hist_all[b] = 0u; g_hist_t[b] = 0u; }
        g_done = 0u;
    }
}

extern "C" void kernel_launch(void* const* d_in, const int* in_sizes, int n_in,
                              void* d_out, int out_size) {
    const float* output = (const float*)d_in[0];
    const int*   target = (const int*)d_in[1];
    if (n_in >= 2 && in_sizes[0] == NROWS && in_sizes[1] == NELEM) {
        output = (const float*)d_in[1];
        target = (const int*)d_in[0];
    }
    auc_kernel<<<NBLK, BLOCK>>>((const float4*)output, output, target,
                                (float*)d_out);
}